// round 5
// baseline (speedup 1.0000x reference)
#include <cuda_runtime.h>
#include <cuda_bf16.h>
#include <cstdint>

// ============================================================================
// CandidateScorer — split-precision bf16 via mma.sync.m16n8k16 (plain sm_103
// PTX target: no tcgen05/wgmma available in this build pipeline).
//   scores = relu(relu(X W1 + b1) W2 + b2) W3 + b3
// Each fp32 operand is split x = hi + lo (two bf16); GEMMs computed as
// Ah*Bh + Ah*Bl + Al*Bh accumulated in fp32 registers (3 MMA passes).
// GEMM2 fuses bias+relu+W3 dot into the epilogue (H2 never materialized).
// ============================================================================

#define N_CAND 65536
#define K1     832
#define HID    1024
#define BOARD_SQ 361

#define M_TILE 128
#define N_TILE 256
#define KCH    64            // 64 bf16 = 128 bytes per row
#define THREADS 256

#define A_ST_BYTES (M_TILE * 128)                      // 16384 per component
#define B_ST_BYTES (N_TILE * 128)                      // 32768 per component
#define STAGE_BYTES (2 * A_ST_BYTES + 2 * B_ST_BYTES)  // 98304
#define SMEM_TOTAL (2 * STAGE_BYTES)                   // 196608

// ---------------------------------------------------------------------------
// Scratch (allocation-free rule: __device__ globals)
// ---------------------------------------------------------------------------
__device__ __nv_bfloat16 g_X_hi[(size_t)N_CAND * K1];
__device__ __nv_bfloat16 g_X_lo[(size_t)N_CAND * K1];
__device__ __nv_bfloat16 g_W1t_hi[(size_t)HID * K1];   // [n][k] K-major
__device__ __nv_bfloat16 g_W1t_lo[(size_t)HID * K1];
__device__ __nv_bfloat16 g_W2t_hi[(size_t)HID * HID];
__device__ __nv_bfloat16 g_W2t_lo[(size_t)HID * HID];
__device__ __nv_bfloat16 g_H_hi[(size_t)N_CAND * HID];
__device__ __nv_bfloat16 g_H_lo[(size_t)N_CAND * HID];
__device__ float g_pf_t[BOARD_SQ * 256];               // transposed feat map
__device__ float g_gpool[256];
__device__ float g_part[4 * (size_t)N_CAND];           // HID/N_TILE = 4 tiles

// ---------------------------------------------------------------------------
// PTX helpers (plain-target only: cp.async / ldmatrix / mma.sync)
// ---------------------------------------------------------------------------
__device__ __forceinline__ uint32_t smem_u32(const void* p) {
    uint32_t a;
    asm("{ .reg .u64 t; cvta.to.shared.u64 t, %1; cvt.u32.u64 %0, t; }" : "=r"(a) : "l"(p));
    return a;
}

__device__ __forceinline__ void cp_async16(uint32_t dst, const void* src) {
    asm volatile("cp.async.cg.shared.global [%0], [%1], 16;" :: "r"(dst), "l"(src));
}
#define CP_COMMIT()  asm volatile("cp.async.commit_group;" ::: "memory")
#define CP_WAIT(n)   asm volatile("cp.async.wait_group %0;" :: "n"(n) : "memory")

__device__ __forceinline__ void ldsm_x4(uint32_t& r0, uint32_t& r1, uint32_t& r2,
                                        uint32_t& r3, uint32_t addr) {
    asm volatile("ldmatrix.sync.aligned.m8n8.x4.shared.b16 {%0,%1,%2,%3}, [%4];"
                 : "=r"(r0), "=r"(r1), "=r"(r2), "=r"(r3) : "r"(addr));
}

__device__ __forceinline__ void mma_bf16(float* c, uint32_t a0, uint32_t a1,
                                         uint32_t a2, uint32_t a3,
                                         uint32_t b0, uint32_t b1) {
    asm volatile(
        "mma.sync.aligned.m16n8k16.row.col.f32.bf16.bf16.f32 "
        "{%0,%1,%2,%3}, {%4,%5,%6,%7}, {%8,%9}, {%0,%1,%2,%3};"
        : "+f"(c[0]), "+f"(c[1]), "+f"(c[2]), "+f"(c[3])
        : "r"(a0), "r"(a1), "r"(a2), "r"(a3), "r"(b0), "r"(b1));
}

__device__ __forceinline__ uint32_t swz(uint32_t off) {      // SW128 pattern
    return off ^ ((off >> 3) & 0x70);
}

// ---------------------------------------------------------------------------
// Prep kernels
// ---------------------------------------------------------------------------
__global__ void transpose_pf_kernel(const float* __restrict__ pf) {
    int idx = blockIdx.x * 256 + threadIdx.x;      // pf_t[p][c] = pf[c][p]
    if (idx < BOARD_SQ * 256) {
        int p = idx >> 8, c = idx & 255;
        g_pf_t[idx] = pf[c * BOARD_SQ + p];
    }
}

__global__ void gpool_kernel(const float* __restrict__ pf) {
    int c = threadIdx.x;
    if (c < 256) {
        const float* p = pf + (size_t)c * BOARD_SQ;
        float s = 0.f;
        for (int i = 0; i < BOARD_SQ; i++) s += p[i];
        g_gpool[c] = s * (1.0f / 361.0f);
    }
}

__global__ void buildX_kernel(const float* __restrict__ cand) {
    int gw = (blockIdx.x * blockDim.x + threadIdx.x) >> 5;  // warp per candidate
    int lane = threadIdx.x & 31;
    if (gw >= N_CAND) return;
    const float* cf = cand + (size_t)gw * 64;
    int gr = min(max((int)(cf[5] * 18.0f), 0), 18);
    int gc = min(max((int)(cf[6] * 18.0f), 0), 18);
    int tr = min(max((int)(cf[7] * 18.0f), 0), 18);
    int tc = min(max((int)(cf[8] * 18.0f), 0), 18);
    int go = gr * 19 + gc, to = tr * 19 + tc;
    size_t ob = (size_t)gw * K1;
    for (int k = lane; k < K1; k += 32) {
        float v;
        if (k < 256)       v = g_pf_t[go * 256 + k];
        else if (k < 512)  v = g_pf_t[to * 256 + (k - 256)];
        else if (k < 768)  v = g_gpool[k - 512];
        else               v = cf[k - 768];
        __nv_bfloat16 h = __float2bfloat16(v);
        g_X_hi[ob + k] = h;
        g_X_lo[ob + k] = __float2bfloat16(v - __bfloat162float(h));
    }
}

__global__ void splitW_kernel(const float* __restrict__ W, int K, int N, int which) {
    int i = blockIdx.x * blockDim.x + threadIdx.x;
    if (i >= K * N) return;
    int n = i / K;
    int k = i - n * K;
    float w = W[(size_t)k * N + n];                 // [K,N] -> K-major [n][k]
    __nv_bfloat16 h = __float2bfloat16(w);
    __nv_bfloat16 l = __float2bfloat16(w - __bfloat162float(h));
    if (which == 0) { g_W1t_hi[i] = h; g_W1t_lo[i] = l; }
    else            { g_W2t_hi[i] = h; g_W2t_lo[i] = l; }
}

// ---------------------------------------------------------------------------
// GEMM: D[128x256] = A[128xK] * B[256xK]^T, 3-pass split-precision bf16.
// MODE 0: A=X, B=W1t, epilogue bias+relu -> split-bf16 H
// MODE 1: A=H, B=W2t, epilogue bias+relu -> fused W3 dot partials
// ---------------------------------------------------------------------------
__device__ __forceinline__ void load_stage(uint32_t sbase, const __nv_bfloat16* Ah,
                                           const __nv_bfloat16* Al,
                                           const __nv_bfloat16* Bh,
                                           const __nv_bfloat16* Bl,
                                           int K, int kt, int tid) {
    const int kof = kt * KCH;
    #pragma unroll 2
    for (int e = tid; e < M_TILE * 8; e += THREADS) {        // A: 1024 chunks
        int row = e >> 3, c = e & 7;
        uint32_t off = swz((uint32_t)(row * 128 + c * 16));
        const size_t so = (size_t)row * K + kof + c * 8;
        cp_async16(sbase + off, Ah + so);
        cp_async16(sbase + A_ST_BYTES + off, Al + so);
    }
    #pragma unroll 4
    for (int e = tid; e < N_TILE * 8; e += THREADS) {        // B: 2048 chunks
        int row = e >> 3, c = e & 7;
        uint32_t off = swz((uint32_t)(row * 128 + c * 16));
        const size_t so = (size_t)row * K + kof + c * 8;
        cp_async16(sbase + 2 * A_ST_BYTES + off, Bh + so);
        cp_async16(sbase + 2 * A_ST_BYTES + B_ST_BYTES + off, Bl + so);
    }
}

template <int MODE>
__global__ __launch_bounds__(THREADS, 1)
void gemm_kernel(const float* __restrict__ bias, const float* __restrict__ W3, int K) {
    extern __shared__ char smem[];
    const uint32_t smem_u = smem_u32(smem);
    const int tid = threadIdx.x;
    const int wid = tid >> 5, lid = tid & 31;
    const int wm = wid >> 2, wn = wid & 3;          // warp grid 2(M) x 4(N)
    const int nbase = blockIdx.x * N_TILE;
    const int mbase = blockIdx.y * M_TILE;
    const int g = lid >> 2, t = lid & 3;

    const __nv_bfloat16 *Ah, *Al, *Bh, *Bl;
    if (MODE == 0) { Ah = g_X_hi; Al = g_X_lo; Bh = g_W1t_hi; Bl = g_W1t_lo; }
    else           { Ah = g_H_hi; Al = g_H_lo; Bh = g_W2t_hi; Bl = g_W2t_lo; }
    Ah += (size_t)mbase * K;  Al += (size_t)mbase * K;
    Bh += (size_t)nbase * K;  Bl += (size_t)nbase * K;

    const int nch = K / KCH;
    float acc[4][8][4];
    #pragma unroll
    for (int i = 0; i < 4; i++)
        #pragma unroll
        for (int j = 0; j < 8; j++)
            #pragma unroll
            for (int q = 0; q < 4; q++) acc[i][j][q] = 0.f;

    load_stage(smem_u, Ah, Al, Bh, Bl, K, 0, tid);
    CP_COMMIT();

    const int rlo = lid & 15;
    const uint32_t khalf16 = (uint32_t)((lid >> 4) * 16);

    for (int kt = 0; kt < nch; kt++) {
        if (kt + 1 < nch) {
            load_stage(smem_u + ((kt + 1) & 1) * STAGE_BYTES, Ah, Al, Bh, Bl, K, kt + 1, tid);
            CP_COMMIT();
            CP_WAIT(1);
        } else {
            CP_WAIT(0);
        }
        __syncthreads();

        const uint32_t sb = smem_u + (kt & 1) * STAGE_BYTES;
        #pragma unroll
        for (int s = 0; s < 4; s++) {
            const uint32_t kb = (uint32_t)(s * 32) + khalf16;
            uint32_t Af[4][4], Bx[4][4], By[4][4];
            #pragma unroll
            for (int i = 0; i < 4; i++) {            // A-hi frags
                uint32_t a = sb + swz((uint32_t)((wm * 64 + i * 16 + rlo) * 128) + kb);
                ldsm_x4(Af[i][0], Af[i][1], Af[i][2], Af[i][3], a);
            }
            #pragma unroll
            for (int jj = 0; jj < 4; jj++) {         // B-hi / B-lo frags
                uint32_t ro = swz((uint32_t)((wn * 64 + jj * 16 + rlo) * 128) + kb);
                ldsm_x4(Bx[jj][0], Bx[jj][1], Bx[jj][2], Bx[jj][3],
                        sb + 2 * A_ST_BYTES + ro);
                ldsm_x4(By[jj][0], By[jj][1], By[jj][2], By[jj][3],
                        sb + 2 * A_ST_BYTES + B_ST_BYTES + ro);
            }
            // pass 1: Ah*Bh, pass 2: Ah*Bl
            #pragma unroll
            for (int i = 0; i < 4; i++)
                #pragma unroll
                for (int jj = 0; jj < 4; jj++) {
                    mma_bf16(acc[i][2*jj],   Af[i][0],Af[i][1],Af[i][2],Af[i][3], Bx[jj][0], Bx[jj][2]);
                    mma_bf16(acc[i][2*jj+1], Af[i][0],Af[i][1],Af[i][2],Af[i][3], Bx[jj][1], Bx[jj][3]);
                    mma_bf16(acc[i][2*jj],   Af[i][0],Af[i][1],Af[i][2],Af[i][3], By[jj][0], By[jj][2]);
                    mma_bf16(acc[i][2*jj+1], Af[i][0],Af[i][1],Af[i][2],Af[i][3], By[jj][1], By[jj][3]);
                }
            // pass 3: Al*Bh (reuse Af regs)
            #pragma unroll
            for (int i = 0; i < 4; i++) {
                uint32_t a = sb + A_ST_BYTES + swz((uint32_t)((wm * 64 + i * 16 + rlo) * 128) + kb);
                ldsm_x4(Af[i][0], Af[i][1], Af[i][2], Af[i][3], a);
            }
            #pragma unroll
            for (int i = 0; i < 4; i++)
                #pragma unroll
                for (int jj = 0; jj < 4; jj++) {
                    mma_bf16(acc[i][2*jj],   Af[i][0],Af[i][1],Af[i][2],Af[i][3], Bx[jj][0], Bx[jj][2]);
                    mma_bf16(acc[i][2*jj+1], Af[i][0],Af[i][1],Af[i][2],Af[i][3], Bx[jj][1], Bx[jj][3]);
                }
        }
        __syncthreads();
    }

    // ------------------------------ epilogue ------------------------------
    if (MODE == 0) {
        #pragma unroll
        for (int i = 0; i < 4; i++) {
            int m0 = mbase + wm * 64 + i * 16 + g;
            #pragma unroll
            for (int j = 0; j < 8; j++) {
                int n0 = nbase + wn * 64 + j * 8 + 2 * t;
                float bb0 = __ldg(&bias[n0]), bb1 = __ldg(&bias[n0 + 1]);
                #pragma unroll
                for (int h2 = 0; h2 < 2; h2++) {
                    float v0 = fmaxf(acc[i][j][2*h2]     + bb0, 0.f);
                    float v1 = fmaxf(acc[i][j][2*h2 + 1] + bb1, 0.f);
                    __nv_bfloat16 h0 = __float2bfloat16(v0), h1 = __float2bfloat16(v1);
                    __nv_bfloat162 hp; hp.x = h0; hp.y = h1;
                    __nv_bfloat162 lp;
                    lp.x = __float2bfloat16(v0 - __bfloat162float(h0));
                    lp.y = __float2bfloat16(v1 - __bfloat162float(h1));
                    size_t idx = (size_t)(m0 + 8 * h2) * HID + n0;
                    *reinterpret_cast<__nv_bfloat162*>(g_H_hi + idx) = hp;
                    *reinterpret_cast<__nv_bfloat162*>(g_H_lo + idx) = lp;
                }
            }
        }
    } else {
        __syncthreads();                       // stages dead; overlay reducer
        float (*red)[4] = reinterpret_cast<float(*)[4]>(smem);
        #pragma unroll
        for (int i = 0; i < 4; i++) {
            float d0 = 0.f, d1 = 0.f;
            #pragma unroll
            for (int j = 0; j < 8; j++) {
                int n0 = nbase + wn * 64 + j * 8 + 2 * t;
                float bb0 = __ldg(&bias[n0]), bb1 = __ldg(&bias[n0 + 1]);
                float w0 = __ldg(&W3[n0]),   w1 = __ldg(&W3[n0 + 1]);
                d0 += fmaxf(acc[i][j][0] + bb0, 0.f) * w0 + fmaxf(acc[i][j][1] + bb1, 0.f) * w1;
                d1 += fmaxf(acc[i][j][2] + bb0, 0.f) * w0 + fmaxf(acc[i][j][3] + bb1, 0.f) * w1;
            }
            d0 += __shfl_xor_sync(0xffffffffu, d0, 1);
            d0 += __shfl_xor_sync(0xffffffffu, d0, 2);
            d1 += __shfl_xor_sync(0xffffffffu, d1, 1);
            d1 += __shfl_xor_sync(0xffffffffu, d1, 2);
            if (t == 0) {
                red[wm * 64 + i * 16 + g][wn]     = d0;
                red[wm * 64 + i * 16 + g + 8][wn] = d1;
            }
        }
        __syncthreads();
        if (tid < M_TILE) {
            float s = red[tid][0] + red[tid][1] + red[tid][2] + red[tid][3];
            g_part[(size_t)blockIdx.x * N_CAND + mbase + tid] = s;
        }
    }
}

// ---------------------------------------------------------------------------
// Final reduce: out[m] = b3 + sum over 4 n-tile partials (deterministic)
// ---------------------------------------------------------------------------
__global__ void reduce_kernel(const float* __restrict__ b3, float* __restrict__ out) {
    int m = blockIdx.x * blockDim.x + threadIdx.x;
    if (m < N_CAND) {
        float s = b3[0];
        #pragma unroll
        for (int tt = 0; tt < 4; tt++) s += g_part[(size_t)tt * N_CAND + m];
        out[m] = s;
    }
}

// ---------------------------------------------------------------------------
// Launch
// ---------------------------------------------------------------------------
extern "C" void kernel_launch(void* const* d_in, const int* in_sizes, int n_in,
                              void* d_out, int out_size) {
    const float* pf   = (const float*)d_in[0];   // (256,19,19)
    const float* cand = (const float*)d_in[1];   // (65536,64)
    const float* W1   = (const float*)d_in[2];   // (832,1024)
    const float* b1   = (const float*)d_in[3];
    const float* W2   = (const float*)d_in[4];   // (1024,1024)
    const float* b2   = (const float*)d_in[5];
    const float* W3   = (const float*)d_in[6];   // (1024,1)
    const float* b3   = (const float*)d_in[7];
    float* out = (float*)d_out;
    (void)in_sizes; (void)n_in; (void)out_size;

    (void)cudaFuncSetAttribute(gemm_kernel<0>,
                               cudaFuncAttributeMaxDynamicSharedMemorySize, SMEM_TOTAL);
    (void)cudaFuncSetAttribute(gemm_kernel<1>,
                               cudaFuncAttributeMaxDynamicSharedMemorySize, SMEM_TOTAL);

    transpose_pf_kernel<<<(BOARD_SQ * 256 + 255) / 256, 256>>>(pf);
    gpool_kernel<<<1, 256>>>(pf);
    buildX_kernel<<<N_CAND / 8, 256>>>(cand);
    splitW_kernel<<<(K1 * HID + 255) / 256, 256>>>(W1, K1, HID, 0);
    splitW_kernel<<<(HID * HID + 255) / 256, 256>>>(W2, HID, HID, 1);

    dim3 grid(HID / N_TILE, N_CAND / M_TILE);    // (4, 512)
    gemm_kernel<0><<<grid, THREADS, SMEM_TOTAL>>>(b1, nullptr, K1);
    gemm_kernel<1><<<grid, THREADS, SMEM_TOTAL>>>(b2, W3, HID);

    reduce_kernel<<<(N_CAND + 255) / 256, 256>>>(b3, out);
}

// round 7
// speedup vs baseline: 1.6944x; 1.6944x over previous
#include <cuda_runtime.h>
#include <cuda_bf16.h>
#include <cstdint>

// ============================================================================
// CandidateScorer — split-precision bf16 mma.sync + cp.async.bulk staging.
//   scores = relu(relu(X W1 + b1) W2 + b2) W3 + b3
// All GEMM operands are pre-materialized in gmem in the exact swizzled
// SMEM-image format ([tile][k_chunk][128B-row swizzled image]); the GEMM
// stages each 96KB chunk with 4 cp.async.bulk ops (mbarrier completion)
// instead of 6144 cp.async 16B ops.  3 MMA passes: Ah*Bh + Ah*Bl + Al*Bh.
// GEMM2 fuses bias+relu+W3 into the epilogue (H2 never materialized).
// ============================================================================

#define N_CAND 65536
#define K1     832
#define HID    1024
#define BOARD_SQ 361

#define M_TILE 128
#define N_TILE 256
#define KCH    64               // 64 bf16 = 128 B per row (swizzle atom)
#define THREADS 256
#define NCH1   (K1 / KCH)       // 13
#define NCH2   (HID / KCH)      // 16
#define N_MT   (N_CAND / M_TILE)  // 512
#define N_NT   (HID / N_TILE)     // 4

#define A_IMG  16384            // 128 rows * 128 B
#define B_IMG  32768            // 256 rows * 128 B
#define STAGE_BYTES (2 * A_IMG + 2 * B_IMG)          // 98304
#define SMEM_TOTAL  (1024 + 2 * STAGE_BYTES)         // 197632

// ---------------------------------------------------------------------------
// Scratch (allocation-free rule: __device__ globals), all in tile-image form.
// ---------------------------------------------------------------------------
__device__ __align__(1024) unsigned char g_Xt_hi[(size_t)N_MT * NCH1 * A_IMG];
__device__ __align__(1024) unsigned char g_Xt_lo[(size_t)N_MT * NCH1 * A_IMG];
__device__ __align__(1024) unsigned char g_W1t_hi[(size_t)N_NT * NCH1 * B_IMG];
__device__ __align__(1024) unsigned char g_W1t_lo[(size_t)N_NT * NCH1 * B_IMG];
__device__ __align__(1024) unsigned char g_W2t_hi[(size_t)N_NT * NCH2 * B_IMG];
__device__ __align__(1024) unsigned char g_W2t_lo[(size_t)N_NT * NCH2 * B_IMG];
__device__ __align__(1024) unsigned char g_Ht_hi[(size_t)N_MT * NCH2 * A_IMG];
__device__ __align__(1024) unsigned char g_Ht_lo[(size_t)N_MT * NCH2 * A_IMG];
__device__ float g_pf_t[BOARD_SQ * 256];
__device__ float g_gpool[256];
__device__ float g_part[(size_t)N_NT * N_CAND];

// ---------------------------------------------------------------------------
// PTX helpers (plain-target: cp.async.bulk / mbarrier / ldmatrix / mma.sync)
// ---------------------------------------------------------------------------
__device__ __forceinline__ uint32_t smem_u32(const void* p) {
    uint32_t a;
    asm("{ .reg .u64 t; cvta.to.shared.u64 t, %1; cvt.u32.u64 %0, t; }" : "=r"(a) : "l"(p));
    return a;
}

#define MBARRIER_INIT(mbar, cnt) \
    asm volatile("mbarrier.init.shared.b64 [%0], %1;" \
                 :: "r"((uint32_t)(mbar)), "r"((uint32_t)(cnt)) : "memory")
#define MBARRIER_EXPECT_TX(mbar, bytes) \
    asm volatile("mbarrier.arrive.expect_tx.shared.b64 _, [%0], %1;" \
                 :: "r"((uint32_t)(mbar)), "r"((uint32_t)(bytes)) : "memory")
#define FENCE_PROXY_ASYNC() \
    asm volatile("fence.proxy.async.shared::cta;" ::: "memory")

__device__ __forceinline__ void bulk_g2s(uint32_t dst, const void* src,
                                         uint32_t bytes, uint32_t mbar) {
    asm volatile(
        "cp.async.bulk.shared::cluster.global.mbarrier::complete_tx::bytes "
        "[%0], [%1], %2, [%3];"
        :: "r"(dst), "l"(__cvta_generic_to_global(src)), "r"(bytes), "r"(mbar)
        : "memory");
}

#define MBARRIER_WAIT_PARITY(mbar_smem_addr, phase_parity) do { \
    uint32_t _mbar = (uint32_t)(mbar_smem_addr); \
    uint32_t _parity = (uint32_t)(phase_parity); \
    uint32_t _done; \
    asm volatile( \
        "{\n\t.reg .pred p;\n\t" \
        "mbarrier.try_wait.parity.acquire.cta.shared::cta.b64 p, [%1], %2;\n\t" \
        "selp.b32 %0, 1, 0, p;\n\t}" \
        : "=r"(_done) : "r"(_mbar), "r"(_parity) : "memory"); \
    if (!_done) { \
        asm volatile( \
            "{\n\t.reg .pred P1;\n\t" \
            "WAIT_LOOP_%=:\n\t" \
            "mbarrier.try_wait.parity.acquire.cta.shared::cta.b64 P1, [%0], %1, 0x989680;\n\t" \
            "@P1 bra.uni WAIT_DONE_%=;\n\t" \
            "bra.uni WAIT_LOOP_%=;\n\t" \
            "WAIT_DONE_%=:\n\t}" \
            :: "r"(_mbar), "r"(_parity) : "memory"); \
    } \
} while (0)

__device__ __forceinline__ void ldsm_x4(uint32_t& r0, uint32_t& r1, uint32_t& r2,
                                        uint32_t& r3, uint32_t addr) {
    asm volatile("ldmatrix.sync.aligned.m8n8.x4.shared.b16 {%0,%1,%2,%3}, [%4];"
                 : "=r"(r0), "=r"(r1), "=r"(r2), "=r"(r3) : "r"(addr));
}

__device__ __forceinline__ void mma_bf16(float* c, uint32_t a0, uint32_t a1,
                                         uint32_t a2, uint32_t a3,
                                         uint32_t b0, uint32_t b1) {
    asm volatile(
        "mma.sync.aligned.m16n8k16.row.col.f32.bf16.bf16.f32 "
        "{%0,%1,%2,%3}, {%4,%5,%6,%7}, {%8,%9}, {%0,%1,%2,%3};"
        : "+f"(c[0]), "+f"(c[1]), "+f"(c[2]), "+f"(c[3])
        : "r"(a0), "r"(a1), "r"(a2), "r"(a3), "r"(b0), "r"(b1));
}

__device__ __forceinline__ uint32_t swz(uint32_t off) {      // SW128 pattern
    return off ^ ((off >> 3) & 0x70);
}

__device__ __forceinline__ uint32_t pack_hi(float v0, float v1, float& r0, float& r1) {
    __nv_bfloat162 hp;
    hp.x = __float2bfloat16(v0);
    hp.y = __float2bfloat16(v1);
    r0 = v0 - __bfloat162float(hp.x);
    r1 = v1 - __bfloat162float(hp.y);
    return *reinterpret_cast<uint32_t*>(&hp);
}
__device__ __forceinline__ uint32_t pack_lo(float r0, float r1) {
    __nv_bfloat162 lp;
    lp.x = __float2bfloat16(r0);
    lp.y = __float2bfloat16(r1);
    return *reinterpret_cast<uint32_t*>(&lp);
}

// ---------------------------------------------------------------------------
// Prep 1: transpose policy map + global pool (one launch)
// ---------------------------------------------------------------------------
__global__ void prep_pf_kernel(const float* __restrict__ pf) {
    int b = blockIdx.x, t = threadIdx.x;
    if (b < BOARD_SQ) {
        g_pf_t[b * 256 + t] = pf[(size_t)t * BOARD_SQ + b];   // pf_t[p][c]
    } else {                                                  // b == BOARD_SQ
        const float* p = pf + (size_t)t * BOARD_SQ;
        float s = 0.f;
        for (int i = 0; i < BOARD_SQ; i++) s += p[i];
        g_gpool[t] = s * (1.0f / 361.0f);
    }
}

// ---------------------------------------------------------------------------
// Prep 2: build X directly in tile-image (swizzled) form. Warp per candidate.
// ---------------------------------------------------------------------------
__global__ void buildX_kernel(const float* __restrict__ cand) {
    int gw = (blockIdx.x * blockDim.x + threadIdx.x) >> 5;
    int lane = threadIdx.x & 31;
    if (gw >= N_CAND) return;
    const float* cf = cand + (size_t)gw * 64;
    int gr = min(max((int)(cf[5] * 18.0f), 0), 18);
    int gc = min(max((int)(cf[6] * 18.0f), 0), 18);
    int tr = min(max((int)(cf[7] * 18.0f), 0), 18);
    int tc = min(max((int)(cf[8] * 18.0f), 0), 18);
    int go = gr * 19 + gc, to = tr * 19 + tc;

    const uint32_t rowoff = swz((uint32_t)((gw & 127) * 128 + lane * 4));
    const size_t mt = (size_t)(gw >> 7);

    #pragma unroll
    for (int ch = 0; ch < NCH1; ch++) {
        int k0 = ch * KCH + lane * 2;
        float v0, v1;
        #pragma unroll
        for (int q = 0; q < 2; q++) {
            int k = k0 + q;
            float v;
            if (k < 256)       v = g_pf_t[go * 256 + k];
            else if (k < 512)  v = g_pf_t[to * 256 + (k - 256)];
            else if (k < 768)  v = g_gpool[k - 512];
            else               v = cf[k - 768];
            if (q == 0) v0 = v; else v1 = v;
        }
        float r0, r1;
        uint32_t hp = pack_hi(v0, v1, r0, r1);
        uint32_t lp = pack_lo(r0, r1);
        size_t tb = (mt * NCH1 + ch) * A_IMG + rowoff;
        *reinterpret_cast<uint32_t*>(g_Xt_hi + tb) = hp;
        *reinterpret_cast<uint32_t*>(g_Xt_lo + tb) = lp;
    }
}

// ---------------------------------------------------------------------------
// Prep 3: split W1 & W2 into K-major tile images. Warp per (n, chunk).
// ---------------------------------------------------------------------------
#define W1_WARPS (HID * NCH1)
#define W2_WARPS (HID * NCH2)
__global__ void splitW_kernel(const float* __restrict__ W1, const float* __restrict__ W2) {
    int gw = (blockIdx.x * blockDim.x + threadIdx.x) >> 5;
    int lane = threadIdx.x & 31;
    const float* W; unsigned char *dh, *dl; int nch;
    if (gw < W1_WARPS)       { W = W1; dh = g_W1t_hi; dl = g_W1t_lo; nch = NCH1; }
    else if (gw < W1_WARPS + W2_WARPS) {
        gw -= W1_WARPS;        W = W2; dh = g_W2t_hi; dl = g_W2t_lo; nch = NCH2;
    } else return;
    int n = gw / nch, ch = gw - n * nch;
    int k0 = ch * KCH + lane * 2;
    float w0 = W[(size_t)k0 * HID + n];
    float w1 = W[(size_t)(k0 + 1) * HID + n];
    float r0, r1;
    uint32_t hp = pack_hi(w0, w1, r0, r1);
    uint32_t lp = pack_lo(r0, r1);
    size_t tb = ((size_t)(n >> 8) * nch + ch) * B_IMG
              + swz((uint32_t)((n & 255) * 128 + lane * 4));
    *reinterpret_cast<uint32_t*>(dh + tb) = hp;
    *reinterpret_cast<uint32_t*>(dl + tb) = lp;
}

// ---------------------------------------------------------------------------
// GEMM: D[128x256] = A[128xK] * B[256xK]^T, 3-pass split bf16, bulk staging.
// MODE 0: A=Xt, B=W1t -> H tiles (split bf16, swizzled image)
// MODE 1: A=Ht, B=W2t -> fused bias+relu+W3 dot partials
// ---------------------------------------------------------------------------
template <int MODE>
__global__ __launch_bounds__(THREADS, 1)
void gemm_kernel(const float* __restrict__ bias, const float* __restrict__ W3) {
    constexpr int NCH = MODE ? NCH2 : NCH1;
    extern __shared__ char smem[];
    const uint32_t smem_u = smem_u32(smem);
    const uint32_t stage0 = smem_u + 1024;
    const int tid = threadIdx.x;
    const int wid = tid >> 5, lid = tid & 31;
    const int wm = wid >> 2, wn = wid & 3;          // warp grid 2(M) x 4(N)
    const int nbase = blockIdx.x * N_TILE;
    const int mbase = blockIdx.y * M_TILE;
    const int g = lid >> 2, t = lid & 3;

    const unsigned char* At_h = (MODE ? g_Ht_hi : g_Xt_hi) + (size_t)blockIdx.y * NCH * A_IMG;
    const unsigned char* At_l = (MODE ? g_Ht_lo : g_Xt_lo) + (size_t)blockIdx.y * NCH * A_IMG;
    const unsigned char* Bt_h = (MODE ? g_W2t_hi : g_W1t_hi) + (size_t)blockIdx.x * NCH * B_IMG;
    const unsigned char* Bt_l = (MODE ? g_W2t_lo : g_W1t_lo) + (size_t)blockIdx.x * NCH * B_IMG;

    if (tid == 0) { MBARRIER_INIT(smem_u, 1); MBARRIER_INIT(smem_u + 8, 1); }
    FENCE_PROXY_ASYNC();          // order mbarrier.init (generic proxy) before TMA
    __syncthreads();

    auto issue = [&](int stg, int kt) {
        if (tid == 0) {
            uint32_t mb = smem_u + stg * 8;
            uint32_t sb = stage0 + stg * STAGE_BYTES;
            MBARRIER_EXPECT_TX(mb, STAGE_BYTES);
            bulk_g2s(sb,             At_h + (size_t)kt * A_IMG, A_IMG, mb);
            bulk_g2s(sb + A_IMG,     At_l + (size_t)kt * A_IMG, A_IMG, mb);
            bulk_g2s(sb + 2 * A_IMG, Bt_h + (size_t)kt * B_IMG, B_IMG, mb);
            bulk_g2s(sb + 2 * A_IMG + B_IMG, Bt_l + (size_t)kt * B_IMG, B_IMG, mb);
        }
    };

    float acc[4][8][4];
    #pragma unroll
    for (int i = 0; i < 4; i++)
        #pragma unroll
        for (int j = 0; j < 8; j++)
            #pragma unroll
            for (int q = 0; q < 4; q++) acc[i][j][q] = 0.f;

    issue(0, 0);

    const int rlo = lid & 15;
    const uint32_t khalf16 = (uint32_t)((lid >> 4) * 16);

    for (int kt = 0; kt < NCH; kt++) {
        if (kt + 1 < NCH) issue((kt + 1) & 1, kt + 1);
        MBARRIER_WAIT_PARITY(smem_u + (kt & 1) * 8, (kt >> 1) & 1);

        const uint32_t sb = stage0 + (kt & 1) * STAGE_BYTES;
        #pragma unroll
        for (int s = 0; s < 4; s++) {
            const uint32_t kb = (uint32_t)(s * 32) + khalf16;
            uint32_t Af[4][4], Bx[4][4], By[4][4];
            #pragma unroll
            for (int i = 0; i < 4; i++) {            // A-hi frags
                uint32_t a = sb + swz((uint32_t)((wm * 64 + i * 16 + rlo) * 128) + kb);
                ldsm_x4(Af[i][0], Af[i][1], Af[i][2], Af[i][3], a);
            }
            #pragma unroll
            for (int jj = 0; jj < 4; jj++) {         // B-hi / B-lo frags
                uint32_t ro = swz((uint32_t)((wn * 64 + jj * 16 + rlo) * 128) + kb);
                ldsm_x4(Bx[jj][0], Bx[jj][1], Bx[jj][2], Bx[jj][3],
                        sb + 2 * A_IMG + ro);
                ldsm_x4(By[jj][0], By[jj][1], By[jj][2], By[jj][3],
                        sb + 2 * A_IMG + B_IMG + ro);
            }
            // pass 1: Ah*Bh, pass 2: Ah*Bl
            #pragma unroll
            for (int i = 0; i < 4; i++)
                #pragma unroll
                for (int jj = 0; jj < 4; jj++) {
                    mma_bf16(acc[i][2*jj],   Af[i][0],Af[i][1],Af[i][2],Af[i][3], Bx[jj][0], Bx[jj][2]);
                    mma_bf16(acc[i][2*jj+1], Af[i][0],Af[i][1],Af[i][2],Af[i][3], Bx[jj][1], Bx[jj][3]);
                    mma_bf16(acc[i][2*jj],   Af[i][0],Af[i][1],Af[i][2],Af[i][3], By[jj][0], By[jj][2]);
                    mma_bf16(acc[i][2*jj+1], Af[i][0],Af[i][1],Af[i][2],Af[i][3], By[jj][1], By[jj][3]);
                }
            // pass 3: Al*Bh (reuse Af regs)
            #pragma unroll
            for (int i = 0; i < 4; i++) {
                uint32_t a = sb + A_IMG + swz((uint32_t)((wm * 64 + i * 16 + rlo) * 128) + kb);
                ldsm_x4(Af[i][0], Af[i][1], Af[i][2], Af[i][3], a);
            }
            #pragma unroll
            for (int i = 0; i < 4; i++)
                #pragma unroll
                for (int jj = 0; jj < 4; jj++) {
                    mma_bf16(acc[i][2*jj],   Af[i][0],Af[i][1],Af[i][2],Af[i][3], Bx[jj][0], Bx[jj][2]);
                    mma_bf16(acc[i][2*jj+1], Af[i][0],Af[i][1],Af[i][2],Af[i][3], Bx[jj][1], Bx[jj][3]);
                }
        }
        __syncthreads();
    }

    // ------------------------------ epilogue ------------------------------
    if (MODE == 0) {
        #pragma unroll
        for (int i = 0; i < 4; i++) {
            #pragma unroll
            for (int j = 0; j < 8; j++) {
                int n0 = nbase + wn * 64 + j * 8 + 2 * t;
                float bb0 = __ldg(&bias[n0]), bb1 = __ldg(&bias[n0 + 1]);
                #pragma unroll
                for (int h2 = 0; h2 < 2; h2++) {
                    int m0 = mbase + wm * 64 + i * 16 + g + 8 * h2;
                    float v0 = fmaxf(acc[i][j][2*h2]     + bb0, 0.f);
                    float v1 = fmaxf(acc[i][j][2*h2 + 1] + bb1, 0.f);
                    float r0, r1;
                    uint32_t hp = pack_hi(v0, v1, r0, r1);
                    uint32_t lp = pack_lo(r0, r1);
                    size_t tb = ((size_t)(m0 >> 7) * NCH2 + (n0 >> 6)) * A_IMG
                              + swz((uint32_t)((m0 & 127) * 128 + (n0 & 63) * 2));
                    *reinterpret_cast<uint32_t*>(g_Ht_hi + tb) = hp;
                    *reinterpret_cast<uint32_t*>(g_Ht_lo + tb) = lp;
                }
            }
        }
    } else {
        __syncthreads();                       // stages dead; overlay reducer
        float (*red)[4] = reinterpret_cast<float(*)[4]>(smem + 1024);
        #pragma unroll
        for (int i = 0; i < 4; i++) {
            float d0 = 0.f, d1 = 0.f;
            #pragma unroll
            for (int j = 0; j < 8; j++) {
                int n0 = nbase + wn * 64 + j * 8 + 2 * t;
                float bb0 = __ldg(&bias[n0]), bb1 = __ldg(&bias[n0 + 1]);
                float w0 = __ldg(&W3[n0]),   w1 = __ldg(&W3[n0 + 1]);
                d0 += fmaxf(acc[i][j][0] + bb0, 0.f) * w0 + fmaxf(acc[i][j][1] + bb1, 0.f) * w1;
                d1 += fmaxf(acc[i][j][2] + bb0, 0.f) * w0 + fmaxf(acc[i][j][3] + bb1, 0.f) * w1;
            }
            d0 += __shfl_xor_sync(0xffffffffu, d0, 1);
            d0 += __shfl_xor_sync(0xffffffffu, d0, 2);
            d1 += __shfl_xor_sync(0xffffffffu, d1, 1);
            d1 += __shfl_xor_sync(0xffffffffu, d1, 2);
            if (t == 0) {
                red[wm * 64 + i * 16 + g][wn]     = d0;
                red[wm * 64 + i * 16 + g + 8][wn] = d1;
            }
        }
        __syncthreads();
        if (tid < M_TILE) {
            float s = red[tid][0] + red[tid][1] + red[tid][2] + red[tid][3];
            g_part[(size_t)blockIdx.x * N_CAND + mbase + tid] = s;
        }
    }
}

// ---------------------------------------------------------------------------
// Final reduce: out[m] = b3 + sum over 4 n-tile partials (deterministic)
// ---------------------------------------------------------------------------
__global__ void reduce_kernel(const float* __restrict__ b3, float* __restrict__ out) {
    int m = blockIdx.x * blockDim.x + threadIdx.x;
    if (m < N_CAND) {
        float s = b3[0];
        #pragma unroll
        for (int tt = 0; tt < N_NT; tt++) s += g_part[(size_t)tt * N_CAND + m];
        out[m] = s;
    }
}

// ---------------------------------------------------------------------------
// Launch
// ---------------------------------------------------------------------------
extern "C" void kernel_launch(void* const* d_in, const int* in_sizes, int n_in,
                              void* d_out, int out_size) {
    const float* pf   = (const float*)d_in[0];   // (256,19,19)
    const float* cand = (const float*)d_in[1];   // (65536,64)
    const float* W1   = (const float*)d_in[2];   // (832,1024)
    const float* b1   = (const float*)d_in[3];
    const float* W2   = (const float*)d_in[4];   // (1024,1024)
    const float* b2   = (const float*)d_in[5];
    const float* W3   = (const float*)d_in[6];   // (1024,1)
    const float* b3   = (const float*)d_in[7];
    float* out = (float*)d_out;
    (void)in_sizes; (void)n_in; (void)out_size;

    (void)cudaFuncSetAttribute(gemm_kernel<0>,
                               cudaFuncAttributeMaxDynamicSharedMemorySize, SMEM_TOTAL);
    (void)cudaFuncSetAttribute(gemm_kernel<1>,
                               cudaFuncAttributeMaxDynamicSharedMemorySize, SMEM_TOTAL);

    prep_pf_kernel<<<BOARD_SQ + 1, 256>>>(pf);                       // launch 0
    buildX_kernel<<<N_CAND / 8, 256>>>(cand);                        // launch 1
    {
        int warps = W1_WARPS + W2_WARPS;
        splitW_kernel<<<(warps * 32 + 255) / 256, 256>>>(W1, W2);    // launch 2
    }

    dim3 grid(N_NT, N_CAND / M_TILE);            // (4, 512)
    gemm_kernel<0><<<grid, THREADS, SMEM_TOTAL>>>(b1, nullptr);      // launch 3
    gemm_kernel<1><<<grid, THREADS, SMEM_TOTAL>>>(b2, W3);           // launch 4

    reduce_kernel<<<(N_CAND + 255) / 256, 256>>>(b3, out);           // launch 5
}